// round 1
// baseline (speedup 1.0000x reference)
#include <cuda_runtime.h>
#include <cuda_bf16.h>
#include <cstdint>

#define N_NODES 100000
#define N_EDGES 3200000
#define IN_DIM  128
#define HID     32
#define OUT     12

// ---------------- scratch (allocation-free: __device__ globals) ----------------
__device__ float g_h1 [N_NODES * HID];   // feat @ W1
__device__ float g_agg1[N_NODES * HID];  // layer-1 aggregation, then x1 in place
__device__ float g_deg [N_NODES];        // in-degree (shared by both layers)
__device__ float g_h2 [N_NODES * OUT];   // x1 @ W2

// vectorized global reduction (sm_90+): 1 transaction for 4 floats
__device__ __forceinline__ void red4(float* addr, float4 v) {
    asm volatile("red.global.add.v4.f32 [%0], {%1,%2,%3,%4};"
                 :: "l"(addr), "f"(v.x), "f"(v.y), "f"(v.z), "f"(v.w)
                 : "memory");
}

// ---------------- GEMM 1: h1[N,32] = feat[N,128] @ W1[128,32] ----------------
// 256 threads/block: 8 nodes per block, 32 threads (one per out-col) per node.
__global__ void gemm1_kernel(const float* __restrict__ feat,
                             const float* __restrict__ W1,
                             float* __restrict__ h1) {
    __shared__ float sW[IN_DIM * HID];          // 16 KB
    int tid = threadIdx.x;
    for (int i = tid; i < IN_DIM * HID; i += 256) sW[i] = W1[i];
    __syncthreads();
    int node = blockIdx.x * 8 + (tid >> 5);
    int j = tid & 31;
    if (node >= N_NODES) return;
    const float* frow = feat + (size_t)node * IN_DIM;
    float acc = 0.f;
    #pragma unroll
    for (int k = 0; k < IN_DIM; k++)
        acc = fmaf(frow[k], sW[k * HID + j], acc);   // frow[k] broadcast across warp
    h1[node * HID + j] = acc;
}

// ---------------- degree: deg[dst[e]] += 1 ----------------
__global__ void deg_kernel(const int* __restrict__ dst, float* __restrict__ deg) {
    int e = blockIdx.x * blockDim.x + threadIdx.x;
    if (e < N_EDGES) atomicAdd(deg + dst[e], 1.0f);
}

// ---------------- layer-1 scatter: agg1[dst] += h1[src], 8 v4-reds/edge ----------------
__global__ void scatter1_kernel(const int* __restrict__ src,
                                const int* __restrict__ dst,
                                const float* __restrict__ h1,
                                float* __restrict__ agg1) {
    long long t = (long long)blockIdx.x * blockDim.x + threadIdx.x;
    if (t >= (long long)N_EDGES * 8) return;
    int e = (int)(t >> 3);
    int p = (int)(t & 7);
    int s = src[e], d = dst[e];
    float4 v = *reinterpret_cast<const float4*>(h1 + (size_t)s * HID + p * 4);
    red4(agg1 + (size_t)d * HID + p * 4, v);
}

// ---------------- finalize layer 1 (in place -> x1): relu(agg/deg + b1) ----------------
__global__ void finalize1_kernel(float* __restrict__ agg1,
                                 const float* __restrict__ deg,
                                 const float* __restrict__ b1) {
    int i = blockIdx.x * blockDim.x + threadIdx.x;
    if (i >= N_NODES * HID) return;
    int node = i >> 5;
    float dg = fmaxf(deg[node], 1.0f);
    float v = agg1[i] / dg + b1[i & 31];
    agg1[i] = fmaxf(v, 0.0f);
}

// ---------------- GEMM 2: h2[N,12] = x1[N,32] @ W2[32,12] ----------------
// 256 threads/block: 16 nodes per block, 16 threads per node (12 active).
__global__ void gemm2_kernel(const float* __restrict__ x1,
                             const float* __restrict__ W2,
                             float* __restrict__ h2) {
    __shared__ float sW[HID * OUT];             // 1.5 KB
    int tid = threadIdx.x;
    for (int i = tid; i < HID * OUT; i += 256) sW[i] = W2[i];
    __syncthreads();
    int node = blockIdx.x * 16 + (tid >> 4);
    int j = tid & 15;
    if (node >= N_NODES || j >= OUT) return;
    const float* xrow = x1 + (size_t)node * HID;
    float acc = 0.f;
    #pragma unroll
    for (int k = 0; k < HID; k++)
        acc = fmaf(xrow[k], sW[k * OUT + j], acc);
    h2[node * OUT + j] = acc;
}

// ---------------- layer-2 scatter: out[dst] += h2[src], 3 v4-reds/edge ----------------
__global__ void scatter2_kernel(const int* __restrict__ src,
                                const int* __restrict__ dst,
                                const float* __restrict__ h2,
                                float* __restrict__ out) {
    long long t = (long long)blockIdx.x * blockDim.x + threadIdx.x;
    if (t >= (long long)N_EDGES * 3) return;
    int e = (int)(t / 3);
    int p = (int)(t - (long long)e * 3);
    int s = src[e], d = dst[e];
    float4 v = *reinterpret_cast<const float4*>(h2 + (size_t)s * OUT + p * 4);
    red4(out + (size_t)d * OUT + p * 4, v);
}

// ---------------- finalize layer 2: relu(out/deg + b2) in place ----------------
__global__ void finalize2_kernel(float* __restrict__ out,
                                 const float* __restrict__ deg,
                                 const float* __restrict__ b2) {
    int i = blockIdx.x * blockDim.x + threadIdx.x;
    if (i >= N_NODES * OUT) return;
    int node = i / OUT;
    int j = i - node * OUT;
    float dg = fmaxf(deg[node], 1.0f);
    float v = out[i] / dg + b2[j];
    out[i] = fmaxf(v, 0.0f);
}

// ---------------- launch ----------------
extern "C" void kernel_launch(void* const* d_in, const int* in_sizes, int n_in,
                              void* d_out, int out_size) {
    const float* feat = (const float*)d_in[0];
    const int*   src  = (const int*)  d_in[1];
    const int*   dst  = (const int*)  d_in[2];
    const float* W1   = (const float*)d_in[3];
    const float* b1   = (const float*)d_in[4];
    const float* W2   = (const float*)d_in[5];
    const float* b2   = (const float*)d_in[6];
    float* out = (float*)d_out;

    void *p_agg1 = nullptr, *p_deg = nullptr, *p_h1 = nullptr, *p_h2 = nullptr;
    cudaGetSymbolAddress(&p_agg1, g_agg1);
    cudaGetSymbolAddress(&p_deg,  g_deg);
    cudaGetSymbolAddress(&p_h1,   g_h1);
    cudaGetSymbolAddress(&p_h2,   g_h2);
    float* h1   = (float*)p_h1;
    float* agg1 = (float*)p_agg1;
    float* deg  = (float*)p_deg;
    float* h2   = (float*)p_h2;

    // zero accumulators (memset nodes are graph-capturable)
    cudaMemsetAsync(p_agg1, 0, sizeof(float) * N_NODES * HID, 0);
    cudaMemsetAsync(p_deg,  0, sizeof(float) * N_NODES, 0);
    cudaMemsetAsync(d_out,  0, sizeof(float) * N_NODES * OUT, 0);

    // layer 1
    gemm1_kernel<<<(N_NODES + 7) / 8, 256>>>(feat, W1, h1);
    deg_kernel<<<(N_EDGES + 255) / 256, 256>>>(dst, deg);
    {
        long long work = (long long)N_EDGES * 8;
        scatter1_kernel<<<(unsigned)((work + 255) / 256), 256>>>(src, dst, h1, agg1);
    }
    finalize1_kernel<<<(N_NODES * HID + 255) / 256, 256>>>(agg1, deg, b1);

    // layer 2
    gemm2_kernel<<<(N_NODES + 15) / 16, 256>>>(agg1, W2, h2);
    {
        long long work = (long long)N_EDGES * 3;
        scatter2_kernel<<<(unsigned)((work + 255) / 256), 256>>>(src, dst, h2, out);
    }
    finalize2_kernel<<<(N_NODES * OUT + 255) / 256, 256>>>(out, deg, b2);
}

// round 3
// speedup vs baseline: 1.2580x; 1.2580x over previous
#include <cuda_runtime.h>
#include <cuda_bf16.h>
#include <cstdint>

#define N_NODES 100000
#define N_EDGES 3200000
#define IN_DIM  128
#define HID     32
#define OUT     12

// ---------------- scratch (allocation-free: __device__ globals) ----------------
__device__ float g_h1 [N_NODES * HID];   // feat @ W1
__device__ float g_agg1[N_NODES * HID];  // layer-1 aggregation
__device__ float g_deg [N_NODES];        // in-degree (shared by both layers)
__device__ float g_h2 [N_NODES * OUT];   // relu(norm(agg1)) @ W2

// vectorized global reduction (sm_90+): 1 transaction for 4 floats
__device__ __forceinline__ void red4(float* addr, float4 v) {
    asm volatile("red.global.add.v4.f32 [%0], {%1,%2,%3,%4};"
                 :: "l"(addr), "f"(v.x), "f"(v.y), "f"(v.z), "f"(v.w)
                 : "memory");
}
__device__ __forceinline__ void red1(float* addr, float v) {
    asm volatile("red.global.add.f32 [%0], %1;" :: "l"(addr), "f"(v) : "memory");
}

// ---------------- GEMM 1: h1[N,32] = feat[N,128] @ W1[128,32] ----------------
// 256 threads/block: 32 nodes/block, 8 threads per node, 4 output cols each.
__global__ void gemm1_kernel(const float* __restrict__ feat,
                             const float* __restrict__ W1,
                             float* __restrict__ h1) {
    __shared__ float sW[IN_DIM * HID];          // 16 KB
    int tid = threadIdx.x;
    for (int i = tid; i < IN_DIM * HID; i += 256) sW[i] = W1[i];
    __syncthreads();
    int node = blockIdx.x * 32 + (tid >> 3);
    if (node >= N_NODES) return;
    int jj = (tid & 7) * 4;
    const float4* frow = reinterpret_cast<const float4*>(feat + (size_t)node * IN_DIM);
    float4 acc = make_float4(0.f, 0.f, 0.f, 0.f);
    #pragma unroll
    for (int k4 = 0; k4 < IN_DIM / 4; k4++) {
        float4 f = frow[k4];
        #pragma unroll
        for (int u = 0; u < 4; u++) {
            float fk = (u == 0) ? f.x : (u == 1) ? f.y : (u == 2) ? f.z : f.w;
            float4 w = *reinterpret_cast<const float4*>(&sW[(k4 * 4 + u) * HID + jj]);
            acc.x = fmaf(fk, w.x, acc.x);
            acc.y = fmaf(fk, w.y, acc.y);
            acc.z = fmaf(fk, w.z, acc.z);
            acc.w = fmaf(fk, w.w, acc.w);
        }
    }
    *reinterpret_cast<float4*>(h1 + (size_t)node * HID + jj) = acc;
}

// ---------------- layer-1 scatter + degree ----------------
// thread t: edge e = t>>3, chunk p = t&7. Chunk 0 also accumulates degree.
// Warp = 4 edges x 8 chunks: index loads hit one sector; gather covers full
// 128B rows (8 lanes/row) -> minimal L1tex wavefronts.
__global__ void scatter1_kernel(const int* __restrict__ src,
                                const int* __restrict__ dst,
                                const float* __restrict__ h1,
                                float* __restrict__ agg1,
                                float* __restrict__ deg) {
    long long t = (long long)blockIdx.x * blockDim.x + threadIdx.x;
    if (t >= (long long)N_EDGES * 8) return;
    int e = (int)(t >> 3);
    int p = (int)(t & 7);
    int s = src[e], d = dst[e];
    float4 v = *reinterpret_cast<const float4*>(h1 + (size_t)s * HID + p * 4);
    red4(agg1 + (size_t)d * HID + p * 4, v);
    if (p == 0) red1(deg + d, 1.0f);
}

// ---------------- fused: x1 = relu(agg1/deg + b1); h2 = x1 @ W2 ----------------
// 256 threads = 8 warps, 1 node per warp.
__global__ void layer_mid_kernel(const float* __restrict__ agg1,
                                 const float* __restrict__ deg,
                                 const float* __restrict__ b1,
                                 const float* __restrict__ W2,
                                 float* __restrict__ h2) {
    __shared__ float sW[HID * OUT];   // 1.5 KB
    __shared__ float sx[8][HID];
    int tid = threadIdx.x;
    for (int i = tid; i < HID * OUT; i += 256) sW[i] = W2[i];
    __syncthreads();
    int w = tid >> 5, lane = tid & 31;
    int node = blockIdx.x * 8 + w;
    if (node < N_NODES) {
        float dg = fmaxf(deg[node], 1.0f);
        float v = agg1[(size_t)node * HID + lane] / dg + b1[lane];
        sx[w][lane] = fmaxf(v, 0.0f);
    }
    __syncwarp();
    if (node < N_NODES && lane < OUT) {
        float acc = 0.f;
        #pragma unroll
        for (int k = 0; k < HID; k++)
            acc = fmaf(sx[w][k], sW[k * OUT + lane], acc);
        h2[(size_t)node * OUT + lane] = acc;
    }
}

// ---------------- layer-2 scatter: out[dst] += h2[src], 3 v4-reds/edge ----------------
__global__ void scatter2_kernel(const int* __restrict__ src,
                                const int* __restrict__ dst,
                                const float* __restrict__ h2,
                                float* __restrict__ out) {
    long long t = (long long)blockIdx.x * blockDim.x + threadIdx.x;
    if (t >= (long long)N_EDGES * 3) return;
    int e = (int)(t / 3);
    int p = (int)(t - (long long)e * 3);
    int s = src[e], d = dst[e];
    float4 v = *reinterpret_cast<const float4*>(h2 + (size_t)s * OUT + p * 4);
    red4(out + (size_t)d * OUT + p * 4, v);
}

// ---------------- finalize layer 2: relu(out/deg + b2) in place ----------------
__global__ void finalize2_kernel(float* __restrict__ out,
                                 const float* __restrict__ deg,
                                 const float* __restrict__ b2) {
    int i = blockIdx.x * blockDim.x + threadIdx.x;
    if (i >= N_NODES * OUT) return;
    int node = i / OUT;
    int j = i - node * OUT;
    float dg = fmaxf(deg[node], 1.0f);
    float v = out[i] / dg + b2[j];
    out[i] = fmaxf(v, 0.0f);
}

// ---------------- launch ----------------
extern "C" void kernel_launch(void* const* d_in, const int* in_sizes, int n_in,
                              void* d_out, int out_size) {
    const float* feat = (const float*)d_in[0];
    const int*   src  = (const int*)  d_in[1];
    const int*   dst  = (const int*)  d_in[2];
    const float* W1   = (const float*)d_in[3];
    const float* b1   = (const float*)d_in[4];
    const float* W2   = (const float*)d_in[5];
    const float* b2   = (const float*)d_in[6];
    float* out = (float*)d_out;

    void *p_agg1 = nullptr, *p_deg = nullptr, *p_h1 = nullptr, *p_h2 = nullptr;
    cudaGetSymbolAddress(&p_agg1, g_agg1);
    cudaGetSymbolAddress(&p_deg,  g_deg);
    cudaGetSymbolAddress(&p_h1,   g_h1);
    cudaGetSymbolAddress(&p_h2,   g_h2);
    float* h1   = (float*)p_h1;
    float* agg1 = (float*)p_agg1;
    float* deg  = (float*)p_deg;
    float* h2   = (float*)p_h2;

    // zero accumulators (memset nodes are graph-capturable)
    cudaMemsetAsync(p_agg1, 0, sizeof(float) * N_NODES * HID, 0);
    cudaMemsetAsync(p_deg,  0, sizeof(float) * N_NODES, 0);
    cudaMemsetAsync(d_out,  0, sizeof(float) * N_NODES * OUT, 0);

    // layer 1
    gemm1_kernel<<<(N_NODES + 31) / 32, 256>>>(feat, W1, h1);
    {
        long long work = (long long)N_EDGES * 8;
        scatter1_kernel<<<(unsigned)((work + 255) / 256), 256>>>(src, dst, h1, agg1, deg);
    }
    layer_mid_kernel<<<(N_NODES + 7) / 8, 256>>>(agg1, deg, b1, W2, h2);

    // layer 2
    {
        long long work = (long long)N_EDGES * 3;
        scatter2_kernel<<<(unsigned)((work + 255) / 256), 256>>>(src, dst, h2, out);
    }
    finalize2_kernel<<<(N_NODES * OUT + 255) / 256, 256>>>(out, deg, b2);
}